// round 16
// baseline (speedup 1.0000x reference)
#include <cuda_runtime.h>
#include <cuda_bf16.h>
#include <math.h>
#include <stdint.h>

#define Bb 2
#define Nn 2048
#define Cc 1024
#define Hh 16
#define HD 64

// Scratch (device globals; no runtime allocation allowed)
__device__ __nv_bfloat16 g_qh[Bb*Hh*Nn*HD], g_ql[Bb*Hh*Nn*HD];
__device__ __nv_bfloat16 g_kh[Bb*Hh*Nn*HD], g_kl[Bb*Hh*Nn*HD];
__device__ __nv_bfloat16 g_vh[Bb*Hh*Nn*HD], g_vl[Bb*Hh*Nn*HD];
__device__ float g_ctx[Bb*Nn*Cc];             // tf32-rounded + col-interleaved
__device__ float g_xp[Bb*Nn*Cc];              // prepped x
__device__ float g_wqkvp[3*Cc*Cc];            // prepped W_qkv
__device__ float g_wprojp[Cc*Cc];             // prepped W_proj
__device__ unsigned int g_maskbits[Bb*Nn*Nn/32];
__device__ int g_mask_is_u8;

// ---------------------------------------------------------------------------
// Mask dtype probe (1 block; must run before prep_all)
// ---------------------------------------------------------------------------
__global__ void mask_probe(const unsigned int* __restrict__ m) {
    __shared__ int found;
    if (threadIdx.x == 0) found = 0;
    __syncthreads();
    int local = 0;
    for (int i = threadIdx.x; i < 16384; i += blockDim.x) {
        unsigned int w = m[i];
        if ((w & ~0x01010101u) == 0u && (w & 0x01010100u) != 0u) local = 1;
    }
    if (local) atomicOr(&found, 1);
    __syncthreads();
    if (threadIdx.x == 0) g_mask_is_u8 = found;
}

__device__ __forceinline__ unsigned int nib4(unsigned int v) {
    return ((v & 0x01010101u) * 0x01020408u) >> 24;
}

// ---------------------------------------------------------------------------
// helpers
// ---------------------------------------------------------------------------
__device__ __forceinline__ unsigned int f2tf32(float f) {
    unsigned int u;
    asm("cvt.rna.tf32.f32 %0, %1;" : "=r"(u) : "f"(f));
    return u;
}

__device__ __forceinline__ float ex2f(float x) {
    float r;
    asm("ex2.approx.f32 %0, %1;" : "=f"(r) : "f"(x));
    return r;
}

__device__ __forceinline__ void mma_tf32(float c[4], const unsigned int a[4],
                                         const unsigned int b[2]) {
    asm volatile(
        "mma.sync.aligned.m16n8k8.row.col.f32.tf32.tf32.f32 "
        "{%0,%1,%2,%3}, {%4,%5,%6,%7}, {%8,%9}, {%0,%1,%2,%3};"
        : "+f"(c[0]), "+f"(c[1]), "+f"(c[2]), "+f"(c[3])
        : "r"(a[0]), "r"(a[1]), "r"(a[2]), "r"(a[3]), "r"(b[0]), "r"(b[1]));
}

__device__ __forceinline__ void mma_bf16(float c[4], const unsigned int a[4],
                                         const unsigned int b[2]) {
    asm volatile(
        "mma.sync.aligned.m16n8k16.row.col.f32.bf16.bf16.f32 "
        "{%0,%1,%2,%3}, {%4,%5,%6,%7}, {%8,%9}, {%0,%1,%2,%3};"
        : "+f"(c[0]), "+f"(c[1]), "+f"(c[2]), "+f"(c[3])
        : "r"(a[0]), "r"(a[1]), "r"(a[2]), "r"(a[3]), "r"(b[0]), "r"(b[1]));
}

__device__ __forceinline__ void ldsm_x4(unsigned int r[4], unsigned int saddr) {
    asm volatile("ldmatrix.sync.aligned.m8n8.x4.shared.b16 {%0,%1,%2,%3}, [%4];"
        : "=r"(r[0]), "=r"(r[1]), "=r"(r[2]), "=r"(r[3]) : "r"(saddr));
}

__device__ __forceinline__ void ldsm_x4t(unsigned int r[4], unsigned int saddr) {
    asm volatile("ldmatrix.sync.aligned.m8n8.x4.trans.shared.b16 {%0,%1,%2,%3}, [%4];"
        : "=r"(r[0]), "=r"(r[1]), "=r"(r[2]), "=r"(r[3]) : "r"(saddr));
}

__device__ __forceinline__ void cp_async16(unsigned int saddr, const void* g) {
    asm volatile("cp.async.cg.shared.global [%0], [%1], 16;" :: "r"(saddr), "l"(g));
}
#define CP_COMMIT() asm volatile("cp.async.commit_group;")
#define CP_WAIT0()  asm volatile("cp.async.wait_group 0;")

__device__ __forceinline__ unsigned int pack_bf16x2(float lo_elem, float hi_elem) {
    unsigned int u;
    asm("cvt.rn.bf16x2.f32 %0, %1, %2;" : "=r"(u) : "f"(hi_elem), "f"(lo_elem));
    return u;
}

__device__ __forceinline__ float bf16_trunc(float v) {
    return __uint_as_float(__float_as_uint(v) & 0xFFFF0000u);
}

// ---------------------------------------------------------------------------
// Combined preprocess: tf32-round + col-interleave for x/W_qkv/W_proj AND
// mask bit-packing, in ONE grid-strided launch (probe must precede).
// ---------------------------------------------------------------------------
__device__ __forceinline__ void prep_group(const float* __restrict__ s8,
                                           float* __restrict__ d8) {
    const float4* s = (const float4*)s8;
    float4 i0 = s[0], i1 = s[1];
    float4 o0, o1;
    o0.x = __uint_as_float(f2tf32(i0.x));
    o0.y = __uint_as_float(f2tf32(i1.x));
    o0.z = __uint_as_float(f2tf32(i0.y));
    o0.w = __uint_as_float(f2tf32(i1.y));
    o1.x = __uint_as_float(f2tf32(i0.z));
    o1.y = __uint_as_float(f2tf32(i1.z));
    o1.z = __uint_as_float(f2tf32(i0.w));
    o1.w = __uint_as_float(f2tf32(i1.w));
    float4* d = (float4*)d8;
    d[0] = o0; d[1] = o1;
}

#define GX (Bb*Nn*Cc/8)      // 524288
#define GQ (3*Cc*Cc/8)       // 393216
#define GP (Cc*Cc/8)         // 131072
#define GM (Bb*Nn*Nn/32)     // 262144 mask words

__global__ void prep_all(const float* __restrict__ x,
                         const float* __restrict__ wq,
                         const float* __restrict__ wp,
                         const void* __restrict__ mraw) {
    int g = blockIdx.x * blockDim.x + threadIdx.x;
    int stride = gridDim.x * blockDim.x;
    const int total = GX + GQ + GP + GM;
    const int isu8 = g_mask_is_u8;
    for (; g < total; g += stride) {
        if (g < GX) {
            prep_group(x + (size_t)g * 8, g_xp + (size_t)g * 8);
        } else if (g < GX + GQ) {
            int gg = g - GX;
            prep_group(wq + (size_t)gg * 8, g_wqkvp + (size_t)gg * 8);
        } else if (g < GX + GQ + GP) {
            int gg = g - GX - GQ;
            prep_group(wp + (size_t)gg * 8, g_wprojp + (size_t)gg * 8);
        } else {
            int i = g - GX - GQ - GP;        // mask word index
            const uint4* src = (const uint4*)mraw;
            unsigned int w;
            if (isu8) {
                uint4 a = src[i * 2], c = src[i * 2 + 1];
                w = nib4(a.x) | (nib4(a.y) << 4) | (nib4(a.z) << 8) |
                    (nib4(a.w) << 12) | (nib4(c.x) << 16) |
                    (nib4(c.y) << 20) | (nib4(c.z) << 24) | (nib4(c.w) << 28);
            } else {
                w = 0;
#pragma unroll
                for (int jw = 0; jw < 8; jw++) {
                    uint4 v = src[i * 8 + jw];
                    unsigned int nb = (v.x ? 1u : 0u) | (v.y ? 2u : 0u) |
                                      (v.z ? 4u : 0u) | (v.w ? 8u : 0u);
                    w |= nb << (jw * 4);
                }
            }
            g_maskbits[i] = w;
        }
    }
}

// ---------------------------------------------------------------------------
// TF32 GEMM core v4: double-buffered cp.async with ONE __syncthreads per
// iteration (wait -> sync -> issue(next) -> compute). Correctness: the sync
// after this thread's wait certifies (a) every warp's cp.async group landed
// (visibility) and (b) every warp finished compute(it-1), so buf (it+1)%2
// (read by compute(it-1)) is free to refill. 2 CTA/SM retained.
// ---------------------------------------------------------------------------
#define GW 40                 // smem row stride in words
#define GMATB (128*GW*4)      // bytes per matrix per buffer (20480)
#define GEMM_SMEM (4*GMATB)   // 81920 bytes

template <int KDIM>
__device__ __forceinline__ void gemm_core2(const float* __restrict__ ap,
                                           const float* __restrict__ bp,
                                           int m0, int j0, float c[4][4][4]) {
    extern __shared__ unsigned int gsm[];
    const unsigned int sb = (unsigned int)__cvta_generic_to_shared(gsm);
    const int tid = threadIdx.x;
    const int lane = tid & 31, w = tid >> 5;
    const int wm = w >> 2, wn = w & 3;
    const int qr = lane >> 2, qc = lane & 3;

    auto issue = [&](int k0, int buf) {
        unsigned int base = sb + buf * (2 * GMATB);
#pragma unroll
        for (int l = 0; l < 4; l++) {
            int ch = tid + l * 256;            // 1024 chunks per matrix
            int row = ch >> 3, cc = (ch & 7) * 4;
            cp_async16(base + row * (GW * 4) + cc * 4,
                       ap + (size_t)(m0 + row) * KDIM + k0 + cc);
            cp_async16(base + GMATB + row * (GW * 4) + cc * 4,
                       bp + (size_t)(j0 + row) * KDIM + k0 + cc);
        }
        CP_COMMIT();
    };
    issue(0, 0);

    const unsigned int a_off = (wm * 64 + qr) * (GW * 4) + qc * 8;
    const unsigned int b_off = (wn * 32 + qr) * (GW * 4) + qc * 8;
    const int NIT = KDIM / 32;

    for (int it = 0; it < NIT; it++) {
        CP_WAIT0();                            // group 'it' complete (sole pending)
        __syncthreads();                       // visibility + compute(it-1) done
        if (it + 1 < NIT) issue((it + 1) * 32, (it + 1) & 1);

        unsigned int bufb = sb + (it & 1) * (2 * GMATB);
        unsigned int abase = bufb + a_off;
        unsigned int bbase = bufb + GMATB + b_off;
#pragma unroll
        for (int ks = 0; ks < 4; ks++) {
            unsigned int a[4][4], bf[4][2];
#pragma unroll
            for (int mt = 0; mt < 4; mt++) {
                unsigned int lo0, lo1, hi0, hi1;
                asm volatile("ld.shared.v2.u32 {%0,%1}, [%2];"
                    : "=r"(lo0), "=r"(lo1)
                    : "r"(abase + mt * 16 * (GW * 4) + ks * 32));
                asm volatile("ld.shared.v2.u32 {%0,%1}, [%2];"
                    : "=r"(hi0), "=r"(hi1)
                    : "r"(abase + (mt * 16 + 8) * (GW * 4) + ks * 32));
                a[mt][0] = lo0; a[mt][1] = hi0; a[mt][2] = lo1; a[mt][3] = hi1;
            }
#pragma unroll
            for (int jt = 0; jt < 4; jt++) {
                unsigned int b0, b1;
                asm volatile("ld.shared.v2.u32 {%0,%1}, [%2];"
                    : "=r"(b0), "=r"(b1)
                    : "r"(bbase + jt * 8 * (GW * 4) + ks * 32));
                bf[jt][0] = b0; bf[jt][1] = b1;
            }
#pragma unroll
            for (int mt = 0; mt < 4; mt++)
#pragma unroll
                for (int jt = 0; jt < 4; jt++)
                    mma_tf32(c[mt][jt], a[mt], bf[jt]);
        }
    }
}

// QKV GEMM; scatter split-bf16 q/k/v. q scaled by 0.125*log2(e).
__global__ __launch_bounds__(256, 2) void gemm_qkv() {
    const int tid = threadIdx.x;
    const int lane = tid & 31, w = tid >> 5;
    const int wm = w >> 2, wn = w & 3;
    const int qr = lane >> 2, qc = lane & 3;
    const int m0 = blockIdx.y * 128;
    const int j0 = blockIdx.x * 128;

    float c[4][4][4];
#pragma unroll
    for (int mt = 0; mt < 4; mt++)
#pragma unroll
        for (int jt = 0; jt < 4; jt++)
#pragma unroll
            for (int r = 0; r < 4; r++) c[mt][jt][r] = 0.f;

    gemm_core2<Cc>(g_xp, g_wqkvp, m0, j0, c);

    const int three = blockIdx.x >> 3;
    __nv_bfloat16* dh = (three == 0) ? g_qh : (three == 1) ? g_kh : g_vh;
    __nv_bfloat16* dl = (three == 0) ? g_ql : (three == 1) ? g_kl : g_vl;
    const float scale = (three == 0) ? 0.18033688f : 1.0f;  // 0.125 * log2(e)
    const int jbase = (j0 & 1023) + wn * 32 + qc * 2;
#pragma unroll
    for (int mt = 0; mt < 4; mt++) {
        int row = m0 + wm * 64 + mt * 16 + qr;
        int b = row >> 11, n = row & 2047;
#pragma unroll
        for (int jt = 0; jt < 4; jt++) {
            int j = jbase + jt * 8;
            int h = j >> 6, hd = j & 63;
            size_t base0 = ((size_t)(b * Hh + h) * Nn + n) * HD + hd;
            size_t base1 = ((size_t)(b * Hh + h) * Nn + (n + 8)) * HD + hd;
            float a0 = c[mt][jt][0] * scale, a1 = c[mt][jt][1] * scale;
            float a2 = c[mt][jt][2] * scale, a3 = c[mt][jt][3] * scale;
            float h0 = bf16_trunc(a0), h1 = bf16_trunc(a1);
            float h2 = bf16_trunc(a2), h3 = bf16_trunc(a3);
            *(unsigned int*)&dh[base0] = pack_bf16x2(h0, h1);
            *(unsigned int*)&dl[base0] = pack_bf16x2(a0 - h0, a1 - h1);
            *(unsigned int*)&dh[base1] = pack_bf16x2(h2, h3);
            *(unsigned int*)&dl[base1] = pack_bf16x2(a2 - h2, a3 - h3);
        }
    }
}

// Output projection (reads interleaved tf32 g_ctx + prepped W_proj).
__global__ __launch_bounds__(256, 2) void gemm_proj(const float* __restrict__ bias,
                                                    float* __restrict__ out) {
    const int tid = threadIdx.x;
    const int lane = tid & 31, w = tid >> 5;
    const int wm = w >> 2, wn = w & 3;
    const int qr = lane >> 2, qc = lane & 3;
    const int m0 = blockIdx.y * 128;
    const int j0 = blockIdx.x * 128;

    float c[4][4][4];
#pragma unroll
    for (int mt = 0; mt < 4; mt++)
#pragma unroll
        for (int jt = 0; jt < 4; jt++)
#pragma unroll
            for (int r = 0; r < 4; r++) c[mt][jt][r] = 0.f;

    gemm_core2<Cc>(g_ctx, g_wprojp, m0, j0, c);

#pragma unroll
    for (int mt = 0; mt < 4; mt++) {
        int row = m0 + wm * 64 + mt * 16 + qr;
#pragma unroll
        for (int jt = 0; jt < 4; jt++) {
            int j = j0 + wn * 32 + jt * 8 + qc * 2;
            float2 bv = *(const float2*)&bias[j];
            float2 v0 = {c[mt][jt][0] + bv.x, c[mt][jt][1] + bv.y};
            float2 v1 = {c[mt][jt][2] + bv.x, c[mt][jt][3] + bv.y};
            *(float2*)&out[(size_t)row * Cc + j] = v0;
            *(float2*)&out[(size_t)(row + 8) * Cc + j] = v1;
        }
    }
}

// ---------------------------------------------------------------------------
// Flash attention v8: R13 compute core + single-sync pipeline
// (wait -> sync -> issue(kt+1) -> compute(kt)).
// ---------------------------------------------------------------------------
#define SKWB 144
#define QH_B 0
#define QL_B 18432
#define KV_B 36864
#define KVBUF_B 36864
#define FLASH_SMEM 110592
#define NT (Nn / 64)

__global__ __launch_bounds__(256, 2) void flash_kernel() {
    extern __shared__ __nv_bfloat16 smB[];
    const unsigned int sbase = (unsigned int)__cvta_generic_to_shared(smB);

    const int tid = threadIdx.x;
    const int w = tid >> 5, lane = tid & 31;
    const int qr = lane >> 2, qc = lane & 3;
    const int bh = blockIdx.y;
    const int b = bh >> 4, h = bh & 15;
    const int q0 = blockIdx.x * 128;
    const int r0 = w * 16;

    const __nv_bfloat16* qgh = g_qh + ((size_t)bh * Nn + q0) * HD;
    const __nv_bfloat16* qgl = g_ql + ((size_t)bh * Nn + q0) * HD;
    const __nv_bfloat16* kgh = g_kh + (size_t)bh * Nn * HD;
    const __nv_bfloat16* kgl = g_kl + (size_t)bh * Nn * HD;
    const __nv_bfloat16* vgh = g_vh + (size_t)bh * Nn * HD;
    const __nv_bfloat16* vgl = g_vl + (size_t)bh * Nn * HD;

#pragma unroll
    for (int l = 0; l < 4; l++) {
        int idx = tid + l * 256;
        int row = idx >> 3, c16 = (idx & 7) * 16, c8 = (idx & 7) * 8;
        cp_async16(sbase + QH_B + row * SKWB + c16, qgh + row * HD + c8);
        cp_async16(sbase + QL_B + row * SKWB + c16, qgl + row * HD + c8);
    }

    auto issue_kv = [&](int kt, int buf) {
        unsigned int bb = sbase + KV_B + buf * KVBUF_B;
#pragma unroll
        for (int l = 0; l < 2; l++) {
            int ch = tid + l * 256;
            int row = ch >> 3, c16 = (ch & 7) * 16, c8 = (ch & 7) * 8;
            size_t go = (size_t)(kt * 64 + row) * HD + c8;
            unsigned int so = bb + row * SKWB + c16;
            cp_async16(so,         kgh + go);
            cp_async16(so + 9216,  kgl + go);
            cp_async16(so + 18432, vgh + go);
            cp_async16(so + 27648, vgl + go);
        }
        CP_COMMIT();
    };
    issue_kv(0, 0);   // group also covers Q fill

    const unsigned int q_lane =
        sbase + QH_B + (r0 + (lane & 15)) * SKWB + (lane >> 4) * 16;
    const unsigned int k_lane_off =
        ((lane & 7) + ((lane >> 4) & 1) * 8) * SKWB + ((lane >> 3) & 1) * 16;
    const unsigned int v_lane_off =
        ((lane & 7) + ((lane >> 3) & 1) * 8) * SKWB + ((lane >> 4) & 1) * 16;

    float st_l0 = 0.f, st_l1 = 0.f;
    float o[8][4];
#pragma unroll
    for (int t = 0; t < 8; t++)
#pragma unroll
        for (int r = 0; r < 4; r++) o[t][r] = 0.f;

    const unsigned int* mb0 =
        g_maskbits + ((size_t)(b * Nn) + q0 + r0 + qr) * 64;
    const unsigned int* mb1 = mb0 + 8 * 64;
    const int sh = 2 * qc;

    for (int kt = 0; kt < NT; kt++) {
        const int cur = kt & 1;
        uint2 mw0 = *(const uint2*)(mb0 + kt * 2);
        uint2 mw1 = *(const uint2*)(mb1 + kt * 2);

        CP_WAIT0();                            // buf cur complete (sole pending)
        __syncthreads();                       // visibility + compute(kt-1) done
        if (kt + 1 < NT) issue_kv(kt + 1, cur ^ 1);

        const unsigned int kbase = sbase + KV_B + cur * KVBUF_B;
        const unsigned int vbase = kbase + 18432;

        // ---- S = Q K^T (3-term split bf16, ldmatrix fragments) ----
        float sc[8][4];
#pragma unroll
        for (int n = 0; n < 8; n++)
#pragma unroll
            for (int r = 0; r < 4; r++) sc[n][r] = 0.f;
#pragma unroll
        for (int ks = 0; ks < 4; ks++) {
            unsigned int ahf[4], alf[4];
            ldsm_x4(ahf, q_lane + ks * 32);
            ldsm_x4(alf, q_lane + (QL_B - QH_B) + ks * 32);
#pragma unroll
            for (int n16 = 0; n16 < 4; n16++) {
                unsigned int bh4[4], bl4[4];
                unsigned int ka = kbase + k_lane_off + n16 * (16 * SKWB) + ks * 32;
                ldsm_x4(bh4, ka);
                ldsm_x4(bl4, ka + 9216);
                mma_bf16(sc[2 * n16],     ahf, &bh4[0]);
                mma_bf16(sc[2 * n16],     alf, &bh4[0]);
                mma_bf16(sc[2 * n16],     ahf, &bl4[0]);
                mma_bf16(sc[2 * n16 + 1], ahf, &bh4[2]);
                mma_bf16(sc[2 * n16 + 1], alf, &bh4[2]);
                mma_bf16(sc[2 * n16 + 1], ahf, &bl4[2]);
            }
        }

        // ---- fused per-ks softmax (ex2.approx) + P V ----
#pragma unroll
        for (int ks = 0; ks < 4; ks++) {
            unsigned int ah2[4], al2[4];
#pragma unroll
            for (int j = 0; j < 2; j++) {
                const int n = 2 * ks + j;
                float p0 = ex2f(sc[n][0]);
                float p1 = ex2f(sc[n][1]);
                float p2 = ex2f(sc[n][2]);
                float p3 = ex2f(sc[n][3]);
                unsigned int x0 = (n < 4) ? mw0.x : mw0.y;
                unsigned int x1 = (n < 4) ? mw1.x : mw1.y;
                int bp = ((n & 3) * 8) + sh;
                p0 = ((x0 >> bp) & 1u) ? p0 : 0.f;
                p1 = ((x0 >> bp) & 2u) ? p1 : 0.f;
                p2 = ((x1 >> bp) & 1u) ? p2 : 0.f;
                p3 = ((x1 >> bp) & 2u) ? p3 : 0.f;
                st_l0 += p0 + p1;
                st_l1 += p2 + p3;
                float h0 = bf16_trunc(p0), h1 = bf16_trunc(p1);
                float h2 = bf16_trunc(p2), h3 = bf16_trunc(p3);
                ah2[2 * j]     = pack_bf16x2(h0, h1);
                al2[2 * j]     = pack_bf16x2(p0 - h0, p1 - h1);
                ah2[2 * j + 1] = pack_bf16x2(h2, h3);
                al2[2 * j + 1] = pack_bf16x2(p2 - h2, p3 - h3);
            }
            unsigned int af[4] = {ah2[0], ah2[1], ah2[2], ah2[3]};
            unsigned int alf2[4] = {al2[0], al2[1], al2[2], al2[3]};
#pragma unroll
            for (int t16 = 0; t16 < 4; t16++) {
                unsigned int vh4[4], vl4[4];
                unsigned int va = vbase + v_lane_off + ks * (16 * SKWB) + t16 * 32;
                ldsm_x4t(vh4, va);
                ldsm_x4t(vl4, va + 9216);
                mma_bf16(o[2 * t16],     af,   &vh4[0]);
                mma_bf16(o[2 * t16],     alf2, &vh4[0]);
                mma_bf16(o[2 * t16],     af,   &vl4[0]);
                mma_bf16(o[2 * t16 + 1], af,   &vh4[2]);
                mma_bf16(o[2 * t16 + 1], alf2, &vh4[2]);
                mma_bf16(o[2 * t16 + 1], af,   &vl4[2]);
            }
        }
    }

    // ---- epilogue: tf32-round + column-interleave for gemm_proj ----
    st_l0 += __shfl_xor_sync(0xffffffffu, st_l0, 1);
    st_l0 += __shfl_xor_sync(0xffffffffu, st_l0, 2);
    st_l1 += __shfl_xor_sync(0xffffffffu, st_l1, 1);
    st_l1 += __shfl_xor_sync(0xffffffffu, st_l1, 2);
    float inv0 = 1.f / st_l0, inv1 = 1.f / st_l1;
    const int c0 = 2 * qc, c1 = 2 * qc + 1;
    const int p0 = (c0 < 4) ? 2 * c0 : 2 * (c0 - 4) + 1;
    const int p1 = (c1 < 4) ? 2 * c1 : 2 * (c1 - 4) + 1;
    size_t ob = ((size_t)(b * Nn + q0 + r0 + qr)) * Cc + h * HD;
#pragma unroll
    for (int t = 0; t < 8; t++) {
        g_ctx[ob + t * 8 + p0] = __uint_as_float(f2tf32(o[t][0] * inv0));
        g_ctx[ob + t * 8 + p1] = __uint_as_float(f2tf32(o[t][1] * inv0));
        g_ctx[ob + 8 * Cc + t * 8 + p0] = __uint_as_float(f2tf32(o[t][2] * inv1));
        g_ctx[ob + 8 * Cc + t * 8 + p1] = __uint_as_float(f2tf32(o[t][3] * inv1));
    }
}

// ---------------------------------------------------------------------------
extern "C" void kernel_launch(void* const* d_in, const int* in_sizes, int n_in,
                              void* d_out, int out_size) {
    const float* x = nullptr;
    const void* mask = nullptr;
    const float* Wqkv = nullptr;
    const float* Wproj = nullptr;
    const float* bproj = nullptr;
    for (int i = 0; i < n_in; i++) {
        switch (in_sizes[i]) {
            case 4194304: x     = (const float*)d_in[i]; break;
            case 8388608: mask  = d_in[i];               break;
            case 3145728: Wqkv  = (const float*)d_in[i]; break;
            case 1048576: Wproj = (const float*)d_in[i]; break;
            case 1024:    bproj = (const float*)d_in[i]; break;
        }
    }
    float* out = (float*)d_out;

    cudaFuncSetAttribute(flash_kernel,
                         cudaFuncAttributeMaxDynamicSharedMemorySize, FLASH_SMEM);
    cudaFuncSetAttribute(gemm_qkv,
                         cudaFuncAttributeMaxDynamicSharedMemorySize, GEMM_SMEM);
    cudaFuncSetAttribute(gemm_proj,
                         cudaFuncAttributeMaxDynamicSharedMemorySize, GEMM_SMEM);

    mask_probe<<<1, 256>>>((const unsigned int*)mask);
    prep_all<<<2048, 256>>>(x, Wqkv, Wproj, mask);
    gemm_qkv<<<dim3(24, 32), 256, GEMM_SMEM>>>();
    flash_kernel<<<dim3(Nn / 128, Bb * Hh), 256, FLASH_SMEM>>>();
    gemm_proj<<<dim3(8, 32), 256, GEMM_SMEM>>>(bproj, out);
}

// round 17
// speedup vs baseline: 1.0149x; 1.0149x over previous
#include <cuda_runtime.h>
#include <cuda_bf16.h>
#include <math.h>
#include <stdint.h>

#define Bb 2
#define Nn 2048
#define Cc 1024
#define Hh 16
#define HD 64

// Scratch (device globals; no runtime allocation allowed)
__device__ __nv_bfloat16 g_qh[Bb*Hh*Nn*HD], g_ql[Bb*Hh*Nn*HD];
__device__ __nv_bfloat16 g_kh[Bb*Hh*Nn*HD], g_kl[Bb*Hh*Nn*HD];
__device__ __nv_bfloat16 g_vh[Bb*Hh*Nn*HD], g_vl[Bb*Hh*Nn*HD];
__device__ float g_ctx[Bb*Nn*Cc];             // tf32-rounded + col-interleaved
__device__ float g_xp[Bb*Nn*Cc];              // prepped x
__device__ float g_wqkvp[3*Cc*Cc];            // prepped W_qkv
__device__ float g_wprojp[Cc*Cc];             // prepped W_proj
__device__ unsigned int g_maskbits[Bb*Nn*Nn/32];
__device__ int g_mask_is_u8;

// ---------------------------------------------------------------------------
// Mask dtype probe (1 block; must run before prep_all)
// ---------------------------------------------------------------------------
__global__ void mask_probe(const unsigned int* __restrict__ m) {
    __shared__ int found;
    if (threadIdx.x == 0) found = 0;
    __syncthreads();
    int local = 0;
    for (int i = threadIdx.x; i < 16384; i += blockDim.x) {
        unsigned int w = m[i];
        if ((w & ~0x01010101u) == 0u && (w & 0x01010100u) != 0u) local = 1;
    }
    if (local) atomicOr(&found, 1);
    __syncthreads();
    if (threadIdx.x == 0) g_mask_is_u8 = found;
}

__device__ __forceinline__ unsigned int nib4(unsigned int v) {
    return ((v & 0x01010101u) * 0x01020408u) >> 24;
}

// ---------------------------------------------------------------------------
// helpers
// ---------------------------------------------------------------------------
__device__ __forceinline__ unsigned int f2tf32(float f) {
    unsigned int u;
    asm("cvt.rna.tf32.f32 %0, %1;" : "=r"(u) : "f"(f));
    return u;
}

__device__ __forceinline__ float ex2f(float x) {
    float r;
    asm("ex2.approx.f32 %0, %1;" : "=f"(r) : "f"(x));
    return r;
}

__device__ __forceinline__ void mma_tf32(float c[4], const unsigned int a[4],
                                         const unsigned int b[2]) {
    asm volatile(
        "mma.sync.aligned.m16n8k8.row.col.f32.tf32.tf32.f32 "
        "{%0,%1,%2,%3}, {%4,%5,%6,%7}, {%8,%9}, {%0,%1,%2,%3};"
        : "+f"(c[0]), "+f"(c[1]), "+f"(c[2]), "+f"(c[3])
        : "r"(a[0]), "r"(a[1]), "r"(a[2]), "r"(a[3]), "r"(b[0]), "r"(b[1]));
}

__device__ __forceinline__ void mma_bf16(float c[4], const unsigned int a[4],
                                         const unsigned int b[2]) {
    asm volatile(
        "mma.sync.aligned.m16n8k16.row.col.f32.bf16.bf16.f32 "
        "{%0,%1,%2,%3}, {%4,%5,%6,%7}, {%8,%9}, {%0,%1,%2,%3};"
        : "+f"(c[0]), "+f"(c[1]), "+f"(c[2]), "+f"(c[3])
        : "r"(a[0]), "r"(a[1]), "r"(a[2]), "r"(a[3]), "r"(b[0]), "r"(b[1]));
}

__device__ __forceinline__ void ldsm_x4(unsigned int r[4], unsigned int saddr) {
    asm volatile("ldmatrix.sync.aligned.m8n8.x4.shared.b16 {%0,%1,%2,%3}, [%4];"
        : "=r"(r[0]), "=r"(r[1]), "=r"(r[2]), "=r"(r[3]) : "r"(saddr));
}

__device__ __forceinline__ void ldsm_x4t(unsigned int r[4], unsigned int saddr) {
    asm volatile("ldmatrix.sync.aligned.m8n8.x4.trans.shared.b16 {%0,%1,%2,%3}, [%4];"
        : "=r"(r[0]), "=r"(r[1]), "=r"(r[2]), "=r"(r[3]) : "r"(saddr));
}

__device__ __forceinline__ void cp_async16(unsigned int saddr, const void* g) {
    asm volatile("cp.async.cg.shared.global [%0], [%1], 16;" :: "r"(saddr), "l"(g));
}
#define CP_COMMIT() asm volatile("cp.async.commit_group;")
#define CP_WAIT1()  asm volatile("cp.async.wait_group 1;")
#define CP_WAIT0()  asm volatile("cp.async.wait_group 0;")

__device__ __forceinline__ unsigned int pack_bf16x2(float lo_elem, float hi_elem) {
    unsigned int u;
    asm("cvt.rn.bf16x2.f32 %0, %1, %2;" : "=r"(u) : "f"(hi_elem), "f"(lo_elem));
    return u;
}

__device__ __forceinline__ float bf16_trunc(float v) {
    return __uint_as_float(__float_as_uint(v) & 0xFFFF0000u);
}

// ---------------------------------------------------------------------------
// Combined preprocess: tf32-round + col-interleave for x/W_qkv/W_proj AND
// mask bit-packing, in ONE grid-strided launch (probe must precede).
// ---------------------------------------------------------------------------
__device__ __forceinline__ void prep_group(const float* __restrict__ s8,
                                           float* __restrict__ d8) {
    const float4* s = (const float4*)s8;
    float4 i0 = s[0], i1 = s[1];
    float4 o0, o1;
    o0.x = __uint_as_float(f2tf32(i0.x));
    o0.y = __uint_as_float(f2tf32(i1.x));
    o0.z = __uint_as_float(f2tf32(i0.y));
    o0.w = __uint_as_float(f2tf32(i1.y));
    o1.x = __uint_as_float(f2tf32(i0.z));
    o1.y = __uint_as_float(f2tf32(i1.z));
    o1.z = __uint_as_float(f2tf32(i0.w));
    o1.w = __uint_as_float(f2tf32(i1.w));
    float4* d = (float4*)d8;
    d[0] = o0; d[1] = o1;
}

#define GX (Bb*Nn*Cc/8)      // 524288
#define GQ (3*Cc*Cc/8)       // 393216
#define GP (Cc*Cc/8)         // 131072
#define GM (Bb*Nn*Nn/32)     // 262144 mask words

__global__ void prep_all(const float* __restrict__ x,
                         const float* __restrict__ wq,
                         const float* __restrict__ wp,
                         const void* __restrict__ mraw) {
    int g = blockIdx.x * blockDim.x + threadIdx.x;
    int stride = gridDim.x * blockDim.x;
    const int total = GX + GQ + GP + GM;
    const int isu8 = g_mask_is_u8;
    for (; g < total; g += stride) {
        if (g < GX) {
            prep_group(x + (size_t)g * 8, g_xp + (size_t)g * 8);
        } else if (g < GX + GQ) {
            int gg = g - GX;
            prep_group(wq + (size_t)gg * 8, g_wqkvp + (size_t)gg * 8);
        } else if (g < GX + GQ + GP) {
            int gg = g - GX - GQ;
            prep_group(wp + (size_t)gg * 8, g_wprojp + (size_t)gg * 8);
        } else {
            int i = g - GX - GQ - GP;        // mask word index
            const uint4* src = (const uint4*)mraw;
            unsigned int w;
            if (isu8) {
                uint4 a = src[i * 2], c = src[i * 2 + 1];
                w = nib4(a.x) | (nib4(a.y) << 4) | (nib4(a.z) << 8) |
                    (nib4(a.w) << 12) | (nib4(c.x) << 16) |
                    (nib4(c.y) << 20) | (nib4(c.z) << 24) | (nib4(c.w) << 28);
            } else {
                w = 0;
#pragma unroll
                for (int jw = 0; jw < 8; jw++) {
                    uint4 v = src[i * 8 + jw];
                    unsigned int nb = (v.x ? 1u : 0u) | (v.y ? 2u : 0u) |
                                      (v.z ? 4u : 0u) | (v.w ? 8u : 0u);
                    w |= nb << (jw * 4);
                }
            }
            g_maskbits[i] = w;
        }
    }
}

// ---------------------------------------------------------------------------
// TF32 GEMM core v2 (R12/R15 config — empirically best for GEMMs):
// cp.async double-buffered at prefetch distance 2 (issue it+2, wait_group 1),
// two syncs per iteration. LDS.64 fragments (stride 40 words). 2 CTA/SM.
// ---------------------------------------------------------------------------
#define GW 40                 // smem row stride in words
#define GMATB (128*GW*4)      // bytes per matrix per buffer (20480)
#define GEMM_SMEM (4*GMATB)   // 81920 bytes

template <int KDIM>
__device__ __forceinline__ void gemm_core2(const float* __restrict__ ap,
                                           const float* __restrict__ bp,
                                           int m0, int j0, float c[4][4][4]) {
    extern __shared__ unsigned int gsm[];
    const unsigned int sb = (unsigned int)__cvta_generic_to_shared(gsm);
    const int tid = threadIdx.x;
    const int lane = tid & 31, w = tid >> 5;
    const int wm = w >> 2, wn = w & 3;
    const int qr = lane >> 2, qc = lane & 3;

    auto issue = [&](int k0, int buf) {
        unsigned int base = sb + buf * (2 * GMATB);
#pragma unroll
        for (int l = 0; l < 4; l++) {
            int ch = tid + l * 256;            // 1024 chunks per matrix
            int row = ch >> 3, cc = (ch & 7) * 4;
            cp_async16(base + row * (GW * 4) + cc * 4,
                       ap + (size_t)(m0 + row) * KDIM + k0 + cc);
            cp_async16(base + GMATB + row * (GW * 4) + cc * 4,
                       bp + (size_t)(j0 + row) * KDIM + k0 + cc);
        }
    };
    issue(0, 0); CP_COMMIT();
    issue(32, 1); CP_COMMIT();

    const unsigned int a_off = (wm * 64 + qr) * (GW * 4) + qc * 8;
    const unsigned int b_off = (wn * 32 + qr) * (GW * 4) + qc * 8;
    const int NIT = KDIM / 32;

    for (int it = 0; it < NIT; it++) {
        CP_WAIT1();
        __syncthreads();
        unsigned int bufb = sb + (it & 1) * (2 * GMATB);
        unsigned int abase = bufb + a_off;
        unsigned int bbase = bufb + GMATB + b_off;
#pragma unroll
        for (int ks = 0; ks < 4; ks++) {
            unsigned int a[4][4], bf[4][2];
#pragma unroll
            for (int mt = 0; mt < 4; mt++) {
                unsigned int lo0, lo1, hi0, hi1;
                asm volatile("ld.shared.v2.u32 {%0,%1}, [%2];"
                    : "=r"(lo0), "=r"(lo1)
                    : "r"(abase + mt * 16 * (GW * 4) + ks * 32));
                asm volatile("ld.shared.v2.u32 {%0,%1}, [%2];"
                    : "=r"(hi0), "=r"(hi1)
                    : "r"(abase + (mt * 16 + 8) * (GW * 4) + ks * 32));
                a[mt][0] = lo0; a[mt][1] = hi0; a[mt][2] = lo1; a[mt][3] = hi1;
            }
#pragma unroll
            for (int jt = 0; jt < 4; jt++) {
                unsigned int b0, b1;
                asm volatile("ld.shared.v2.u32 {%0,%1}, [%2];"
                    : "=r"(b0), "=r"(b1)
                    : "r"(bbase + jt * 8 * (GW * 4) + ks * 32));
                bf[jt][0] = b0; bf[jt][1] = b1;
            }
#pragma unroll
            for (int mt = 0; mt < 4; mt++)
#pragma unroll
                for (int jt = 0; jt < 4; jt++)
                    mma_tf32(c[mt][jt], a[mt], bf[jt]);
        }
        __syncthreads();
        if (it + 2 < NIT) issue((it + 2) * 32, it & 1);
        CP_COMMIT();
    }
}

// QKV GEMM; scatter split-bf16 q/k/v. q scaled by 0.125*log2(e).
__global__ __launch_bounds__(256, 2) void gemm_qkv() {
    const int tid = threadIdx.x;
    const int lane = tid & 31, w = tid >> 5;
    const int wm = w >> 2, wn = w & 3;
    const int qr = lane >> 2, qc = lane & 3;
    const int m0 = blockIdx.y * 128;
    const int j0 = blockIdx.x * 128;

    float c[4][4][4];
#pragma unroll
    for (int mt = 0; mt < 4; mt++)
#pragma unroll
        for (int jt = 0; jt < 4; jt++)
#pragma unroll
            for (int r = 0; r < 4; r++) c[mt][jt][r] = 0.f;

    gemm_core2<Cc>(g_xp, g_wqkvp, m0, j0, c);

    const int three = blockIdx.x >> 3;
    __nv_bfloat16* dh = (three == 0) ? g_qh : (three == 1) ? g_kh : g_vh;
    __nv_bfloat16* dl = (three == 0) ? g_ql : (three == 1) ? g_kl : g_vl;
    const float scale = (three == 0) ? 0.18033688f : 1.0f;  // 0.125 * log2(e)
    const int jbase = (j0 & 1023) + wn * 32 + qc * 2;
#pragma unroll
    for (int mt = 0; mt < 4; mt++) {
        int row = m0 + wm * 64 + mt * 16 + qr;
        int b = row >> 11, n = row & 2047;
#pragma unroll
        for (int jt = 0; jt < 4; jt++) {
            int j = jbase + jt * 8;
            int h = j >> 6, hd = j & 63;
            size_t base0 = ((size_t)(b * Hh + h) * Nn + n) * HD + hd;
            size_t base1 = ((size_t)(b * Hh + h) * Nn + (n + 8)) * HD + hd;
            float a0 = c[mt][jt][0] * scale, a1 = c[mt][jt][1] * scale;
            float a2 = c[mt][jt][2] * scale, a3 = c[mt][jt][3] * scale;
            float h0 = bf16_trunc(a0), h1 = bf16_trunc(a1);
            float h2 = bf16_trunc(a2), h3 = bf16_trunc(a3);
            *(unsigned int*)&dh[base0] = pack_bf16x2(h0, h1);
            *(unsigned int*)&dl[base0] = pack_bf16x2(a0 - h0, a1 - h1);
            *(unsigned int*)&dh[base1] = pack_bf16x2(h2, h3);
            *(unsigned int*)&dl[base1] = pack_bf16x2(a2 - h2, a3 - h3);
        }
    }
}

// Output projection (reads interleaved tf32 g_ctx + prepped W_proj).
__global__ __launch_bounds__(256, 2) void gemm_proj(const float* __restrict__ bias,
                                                    float* __restrict__ out) {
    const int tid = threadIdx.x;
    const int lane = tid & 31, w = tid >> 5;
    const int wm = w >> 2, wn = w & 3;
    const int qr = lane >> 2, qc = lane & 3;
    const int m0 = blockIdx.y * 128;
    const int j0 = blockIdx.x * 128;

    float c[4][4][4];
#pragma unroll
    for (int mt = 0; mt < 4; mt++)
#pragma unroll
        for (int jt = 0; jt < 4; jt++)
#pragma unroll
            for (int r = 0; r < 4; r++) c[mt][jt][r] = 0.f;

    gemm_core2<Cc>(g_ctx, g_wprojp, m0, j0, c);

#pragma unroll
    for (int mt = 0; mt < 4; mt++) {
        int row = m0 + wm * 64 + mt * 16 + qr;
#pragma unroll
        for (int jt = 0; jt < 4; jt++) {
            int j = j0 + wn * 32 + jt * 8 + qc * 2;
            float2 bv = *(const float2*)&bias[j];
            float2 v0 = {c[mt][jt][0] + bv.x, c[mt][jt][1] + bv.y};
            float2 v1 = {c[mt][jt][2] + bv.x, c[mt][jt][3] + bv.y};
            *(float2*)&out[(size_t)row * Cc + j] = v0;
            *(float2*)&out[(size_t)(row + 8) * Cc + j] = v1;
        }
    }
}

// ---------------------------------------------------------------------------
// Flash attention v8 (R16 config — measured best for flash): R13 compute core
// + single-sync pipeline (wait -> sync -> issue(kt+1) -> compute(kt)).
// ---------------------------------------------------------------------------
#define SKWB 144
#define QH_B 0
#define QL_B 18432
#define KV_B 36864
#define KVBUF_B 36864
#define FLASH_SMEM 110592
#define NT (Nn / 64)

__global__ __launch_bounds__(256, 2) void flash_kernel() {
    extern __shared__ __nv_bfloat16 smB[];
    const unsigned int sbase = (unsigned int)__cvta_generic_to_shared(smB);

    const int tid = threadIdx.x;
    const int w = tid >> 5, lane = tid & 31;
    const int qr = lane >> 2, qc = lane & 3;
    const int bh = blockIdx.y;
    const int b = bh >> 4, h = bh & 15;
    const int q0 = blockIdx.x * 128;
    const int r0 = w * 16;

    const __nv_bfloat16* qgh = g_qh + ((size_t)bh * Nn + q0) * HD;
    const __nv_bfloat16* qgl = g_ql + ((size_t)bh * Nn + q0) * HD;
    const __nv_bfloat16* kgh = g_kh + (size_t)bh * Nn * HD;
    const __nv_bfloat16* kgl = g_kl + (size_t)bh * Nn * HD;
    const __nv_bfloat16* vgh = g_vh + (size_t)bh * Nn * HD;
    const __nv_bfloat16* vgl = g_vl + (size_t)bh * Nn * HD;

#pragma unroll
    for (int l = 0; l < 4; l++) {
        int idx = tid + l * 256;
        int row = idx >> 3, c16 = (idx & 7) * 16, c8 = (idx & 7) * 8;
        cp_async16(sbase + QH_B + row * SKWB + c16, qgh + row * HD + c8);
        cp_async16(sbase + QL_B + row * SKWB + c16, qgl + row * HD + c8);
    }

    auto issue_kv = [&](int kt, int buf) {
        unsigned int bb = sbase + KV_B + buf * KVBUF_B;
#pragma unroll
        for (int l = 0; l < 2; l++) {
            int ch = tid + l * 256;
            int row = ch >> 3, c16 = (ch & 7) * 16, c8 = (ch & 7) * 8;
            size_t go = (size_t)(kt * 64 + row) * HD + c8;
            unsigned int so = bb + row * SKWB + c16;
            cp_async16(so,         kgh + go);
            cp_async16(so + 9216,  kgl + go);
            cp_async16(so + 18432, vgh + go);
            cp_async16(so + 27648, vgl + go);
        }
        CP_COMMIT();
    };
    issue_kv(0, 0);   // group also covers Q fill

    const unsigned int q_lane =
        sbase + QH_B + (r0 + (lane & 15)) * SKWB + (lane >> 4) * 16;
    const unsigned int k_lane_off =
        ((lane & 7) + ((lane >> 4) & 1) * 8) * SKWB + ((lane >> 3) & 1) * 16;
    const unsigned int v_lane_off =
        ((lane & 7) + ((lane >> 3) & 1) * 8) * SKWB + ((lane >> 4) & 1) * 16;

    float st_l0 = 0.f, st_l1 = 0.f;
    float o[8][4];
#pragma unroll
    for (int t = 0; t < 8; t++)
#pragma unroll
        for (int r = 0; r < 4; r++) o[t][r] = 0.f;

    const unsigned int* mb0 =
        g_maskbits + ((size_t)(b * Nn) + q0 + r0 + qr) * 64;
    const unsigned int* mb1 = mb0 + 8 * 64;
    const int sh = 2 * qc;

    for (int kt = 0; kt < NT; kt++) {
        const int cur = kt & 1;
        uint2 mw0 = *(const uint2*)(mb0 + kt * 2);
        uint2 mw1 = *(const uint2*)(mb1 + kt * 2);

        CP_WAIT0();                            // buf cur complete (sole pending)
        __syncthreads();                       // visibility + compute(kt-1) done
        if (kt + 1 < NT) issue_kv(kt + 1, cur ^ 1);

        const unsigned int kbase = sbase + KV_B + cur * KVBUF_B;
        const unsigned int vbase = kbase + 18432;

        // ---- S = Q K^T (3-term split bf16, ldmatrix fragments) ----
        float sc[8][4];
#pragma unroll
        for (int n = 0; n < 8; n++)
#pragma unroll
            for (int r = 0; r < 4; r++) sc[n][r] = 0.f;
#pragma unroll
        for (int ks = 0; ks < 4; ks++) {
            unsigned int ahf[4], alf[4];
            ldsm_x4(ahf, q_lane + ks * 32);
            ldsm_x4(alf, q_lane + (QL_B - QH_B) + ks * 32);
#pragma unroll
            for (int n16 = 0; n16 < 4; n16++) {
                unsigned int bh4[4], bl4[4];
                unsigned int ka = kbase + k_lane_off + n16 * (16 * SKWB) + ks * 32;
                ldsm_x4(bh4, ka);
                ldsm_x4(bl4, ka + 9216);
                mma_bf16(sc[2 * n16],     ahf, &bh4[0]);
                mma_bf16(sc[2 * n16],     alf, &bh4[0]);
                mma_bf16(sc[2 * n16],     ahf, &bl4[0]);
                mma_bf16(sc[2 * n16 + 1], ahf, &bh4[2]);
                mma_bf16(sc[2 * n16 + 1], alf, &bh4[2]);
                mma_bf16(sc[2 * n16 + 1], ahf, &bl4[2]);
            }
        }

        // ---- fused per-ks softmax (ex2.approx) + P V ----
#pragma unroll
        for (int ks = 0; ks < 4; ks++) {
            unsigned int ah2[4], al2[4];
#pragma unroll
            for (int j = 0; j < 2; j++) {
                const int n = 2 * ks + j;
                float p0 = ex2f(sc[n][0]);
                float p1 = ex2f(sc[n][1]);
                float p2 = ex2f(sc[n][2]);
                float p3 = ex2f(sc[n][3]);
                unsigned int x0 = (n < 4) ? mw0.x : mw0.y;
                unsigned int x1 = (n < 4) ? mw1.x : mw1.y;
                int bp = ((n & 3) * 8) + sh;
                p0 = ((x0 >> bp) & 1u) ? p0 : 0.f;
                p1 = ((x0 >> bp) & 2u) ? p1 : 0.f;
                p2 = ((x1 >> bp) & 1u) ? p2 : 0.f;
                p3 = ((x1 >> bp) & 2u) ? p3 : 0.f;
                st_l0 += p0 + p1;
                st_l1 += p2 + p3;
                float h0 = bf16_trunc(p0), h1 = bf16_trunc(p1);
                float h2 = bf16_trunc(p2), h3 = bf16_trunc(p3);
                ah2[2 * j]     = pack_bf16x2(h0, h1);
                al2[2 * j]     = pack_bf16x2(p0 - h0, p1 - h1);
                ah2[2 * j + 1] = pack_bf16x2(h2, h3);
                al2[2 * j + 1] = pack_bf16x2(p2 - h2, p3 - h3);
            }
            unsigned int af[4] = {ah2[0], ah2[1], ah2[2], ah2[3]};
            unsigned int alf2[4] = {al2[0], al2[1], al2[2], al2[3]};
#pragma unroll
            for (int t16 = 0; t16 < 4; t16++) {
                unsigned int vh4[4], vl4[4];
                unsigned int va = vbase + v_lane_off + ks * (16 * SKWB) + t16 * 32;
                ldsm_x4t(vh4, va);
                ldsm_x4t(vl4, va + 9216);
                mma_bf16(o[2 * t16],     af,   &vh4[0]);
                mma_bf16(o[2 * t16],     alf2, &vh4[0]);
                mma_bf16(o[2 * t16],     af,   &vl4[0]);
                mma_bf16(o[2 * t16 + 1], af,   &vh4[2]);
                mma_bf16(o[2 * t16 + 1], alf2, &vh4[2]);
                mma_bf16(o[2 * t16 + 1], af,   &vl4[2]);
            }
        }
    }

    // ---- epilogue: tf32-round + column-interleave for gemm_proj ----
    st_l0 += __shfl_xor_sync(0xffffffffu, st_l0, 1);
    st_l0 += __shfl_xor_sync(0xffffffffu, st_l0, 2);
    st_l1 += __shfl_xor_sync(0xffffffffu, st_l1, 1);
    st_l1 += __shfl_xor_sync(0xffffffffu, st_l1, 2);
    float inv0 = 1.f / st_l0, inv1 = 1.f / st_l1;
    const int c0 = 2 * qc, c1 = 2 * qc + 1;
    const int p0 = (c0 < 4) ? 2 * c0 : 2 * (c0 - 4) + 1;
    const int p1 = (c1 < 4) ? 2 * c1 : 2 * (c1 - 4) + 1;
    size_t ob = ((size_t)(b * Nn + q0 + r0 + qr)) * Cc + h * HD;
#pragma unroll
    for (int t = 0; t < 8; t++) {
        g_ctx[ob + t * 8 + p0] = __uint_as_float(f2tf32(o[t][0] * inv0));
        g_ctx[ob + t * 8 + p1] = __uint_as_float(f2tf32(o[t][1] * inv0));
        g_ctx[ob + 8 * Cc + t * 8 + p0] = __uint_as_float(f2tf32(o[t][2] * inv1));
        g_ctx[ob + 8 * Cc + t * 8 + p1] = __uint_as_float(f2tf32(o[t][3] * inv1));
    }
}

// ---------------------------------------------------------------------------
extern "C" void kernel_launch(void* const* d_in, const int* in_sizes, int n_in,
                              void* d_out, int out_size) {
    const float* x = nullptr;
    const void* mask = nullptr;
    const float* Wqkv = nullptr;
    const float* Wproj = nullptr;
    const float* bproj = nullptr;
    for (int i = 0; i < n_in; i++) {
        switch (in_sizes[i]) {
            case 4194304: x     = (const float*)d_in[i]; break;
            case 8388608: mask  = d_in[i];               break;
            case 3145728: Wqkv  = (const float*)d_in[i]; break;
            case 1048576: Wproj = (const float*)d_in[i]; break;
            case 1024:    bproj = (const float*)d_in[i]; break;
        }
    }
    float* out = (float*)d_out;

    cudaFuncSetAttribute(flash_kernel,
                         cudaFuncAttributeMaxDynamicSharedMemorySize, FLASH_SMEM);
    cudaFuncSetAttribute(gemm_qkv,
                         cudaFuncAttributeMaxDynamicSharedMemorySize, GEMM_SMEM);
    cudaFuncSetAttribute(gemm_proj,
                         cudaFuncAttributeMaxDynamicSharedMemorySize, GEMM_SMEM);

    mask_probe<<<1, 256>>>((const unsigned int*)mask);
    prep_all<<<2048, 256>>>(x, Wqkv, Wproj, mask);
    gemm_qkv<<<dim3(24, 32), 256, GEMM_SMEM>>>();
    flash_kernel<<<dim3(Nn / 128, Bb * Hh), 256, FLASH_SMEM>>>();
    gemm_proj<<<dim3(8, 32), 256, GEMM_SMEM>>>(bproj, out);
}